// round 1
// baseline (speedup 1.0000x reference)
#include <cuda_runtime.h>

#define N_IN    6
#define N_MF    4
#define N_RULES 4096
#define BATCH   4096
#define BT      32            // batch elements per block (one per lane)
#define RCHUNKS 4             // rule chunks (blocks per batch tile)
#define RULES_PER_CHUNK (N_RULES / RCHUNKS)      // 1024
#define WARPS   8
#define RULES_PER_WARP (RULES_PER_CHUNK / WARPS) // 128

// Scratch (static device globals — no allocation)
__device__ float g_coeff8[N_RULES * 8];          // coeff padded 7 -> 8 floats/rule
__device__ float g_part[RCHUNKS][BATCH];         // partial numerators (already / den)

// ---------------------------------------------------------------------------
// Prep: pad coeff rows (N_RULES, 1, 7) -> (N_RULES, 8) for float4 loads
// ---------------------------------------------------------------------------
__global__ void prep_kernel(const float* __restrict__ coeff) {
    int i = blockIdx.x * blockDim.x + threadIdx.x;
    if (i < N_RULES * 8) {
        int r = i >> 3, j = i & 7;
        g_coeff8[i] = (j < 7) ? coeff[r * 7 + j] : 0.0f;
    }
}

// ---------------------------------------------------------------------------
// Main: per block = (batch tile of 32) x (rule chunk of 1024)
// rules[b,r] = P[b, r>>6] * Q[b, r&63]  (digit factorization; mf_indices is
// the full itertools.product enumeration, so r's base-4 digits ARE the MF ids)
// denominator = prod_i sum_m memb[b,i,m]  (separable, exact)
// ---------------------------------------------------------------------------
__global__ void __launch_bounds__(256) anfis_kernel(
    const float* __restrict__ x, const float* __restrict__ a,
    const float* __restrict__ b, const float* __restrict__ c)
{
    __shared__ float Psh[64 * BT];       // [idx][lane]
    __shared__ float Qsh[64 * BT];       // [idx][lane]
    __shared__ float xpsh[7 * BT];       // x_plus, [j][lane]
    __shared__ float rdsh[BT];           // 1/den
    __shared__ float accsh[WARPS][7][BT];

    const int tid    = threadIdx.x;
    const int lane   = tid & 31;
    const int wid    = tid >> 5;
    const int btile  = blockIdx.x & 127;
    const int rchunk = blockIdx.x >> 7;
    const int b0     = btile * BT;

    // ---- Phase 1: membership values, P/Q tables, denominator (32 threads) ----
    if (tid < BT) {
        const int bb = b0 + tid;
        float m[N_IN][N_MF];
        float den = 1.0f;
        #pragma unroll
        for (int i = 0; i < N_IN; i++) {
            float xi = x[bb * N_IN + i];
            xpsh[i * BT + tid] = xi;
            float s = 0.0f;
            #pragma unroll
            for (int k = 0; k < N_MF; k++) {
                float av = a[i * N_MF + k];
                float bv = b[i * N_MF + k];
                float cv = c[i * N_MF + k];
                float d  = (xi - cv) / av;
                float d2 = d * d;
                float db = (bv == 2.0f) ? (d2 * d2) : __powf(d2, bv);
                float mm = 1.0f / (1.0f + db);
                m[i][k] = mm;
                s += mm;
            }
            den *= s;
        }
        xpsh[6 * BT + tid] = 1.0f;
        den = fmaxf(den, 1e-12f);
        rdsh[tid] = 1.0f / den;
        #pragma unroll
        for (int h = 0; h < 64; h++) {
            Psh[h * BT + tid] = m[0][(h >> 4) & 3] * m[1][(h >> 2) & 3] * m[2][h & 3];
            Qsh[h * BT + tid] = m[3][(h >> 4) & 3] * m[4][(h >> 2) & 3] * m[5][h & 3];
        }
    }
    __syncthreads();

    // ---- Phase 2: rule loop. acc_j = sum_r w(b,r) * coeff[r,j] ----
    float acc0 = 0.f, acc1 = 0.f, acc2 = 0.f, acc3 = 0.f,
          acc4 = 0.f, acc5 = 0.f, acc6 = 0.f;
    const int rbase = rchunk * RULES_PER_CHUNK + wid * RULES_PER_WARP;
    const float4* __restrict__ C = reinterpret_cast<const float4*>(g_coeff8);

    #pragma unroll
    for (int hh = 0; hh < RULES_PER_WARP / 64; hh++) {   // 2 high-digit groups
        const int   rhi = (rbase >> 6) + hh;
        const float Pv  = Psh[rhi * BT + lane];
        #pragma unroll 8
        for (int lo = 0; lo < 64; lo++) {
            const int r   = (rhi << 6) + lo;
            const float4 cA = __ldg(&C[2 * r]);
            const float4 cB = __ldg(&C[2 * r + 1]);
            const float  w  = Pv * Qsh[lo * BT + lane];
            acc0 = fmaf(w, cA.x, acc0);
            acc1 = fmaf(w, cA.y, acc1);
            acc2 = fmaf(w, cA.z, acc2);
            acc3 = fmaf(w, cA.w, acc3);
            acc4 = fmaf(w, cB.x, acc4);
            acc5 = fmaf(w, cB.y, acc5);
            acc6 = fmaf(w, cB.z, acc6);
        }
    }

    accsh[wid][0][lane] = acc0;
    accsh[wid][1][lane] = acc1;
    accsh[wid][2][lane] = acc2;
    accsh[wid][3][lane] = acc3;
    accsh[wid][4][lane] = acc4;
    accsh[wid][5][lane] = acc5;
    accsh[wid][6][lane] = acc6;
    __syncthreads();

    // ---- Phase 3: cross-warp reduce, dot with x_plus, scale by 1/den ----
    if (tid < BT) {
        float num = 0.0f;
        #pragma unroll
        for (int j = 0; j < 7; j++) {
            float D = 0.0f;
            #pragma unroll
            for (int w = 0; w < WARPS; w++) D += accsh[w][j][tid];
            num = fmaf(xpsh[j * BT + tid], D, num);
        }
        g_part[rchunk][b0 + tid] = num * rdsh[tid];
    }
}

// ---------------------------------------------------------------------------
// Reduce: deterministic sum of the 4 rule-chunk partials
// ---------------------------------------------------------------------------
__global__ void reduce_kernel(float* __restrict__ out) {
    int i = blockIdx.x * blockDim.x + threadIdx.x;
    if (i < BATCH)
        out[i] = (g_part[0][i] + g_part[1][i]) + (g_part[2][i] + g_part[3][i]);
}

extern "C" void kernel_launch(void* const* d_in, const int* in_sizes, int n_in,
                              void* d_out, int out_size) {
    const float* x     = (const float*)d_in[0];
    const float* a     = (const float*)d_in[1];
    const float* b     = (const float*)d_in[2];
    const float* c     = (const float*)d_in[3];
    const float* coeff = (const float*)d_in[4];
    // d_in[5] = mf_indices (int32): full itertools.product enumeration -> folded
    // into the base-4 digit decode analytically.
    float* out = (float*)d_out;

    prep_kernel<<<(N_RULES * 8 + 255) / 256, 256>>>(coeff);
    anfis_kernel<<<128 * RCHUNKS, 256>>>(x, a, b, c);
    reduce_kernel<<<(BATCH + 255) / 256, 256>>>(out);
}

// round 2
// speedup vs baseline: 1.4118x; 1.4118x over previous
#include <cuda_runtime.h>
#include <cstdint>

#define N_IN    6
#define N_MF    4
#define N_RULES 4096
#define BATCH   4096
#define BT      32                 // batch elements per block (one per lane)
#define NWARPS  16
#define NTHREADS (NWARPS * 32)
#define RULES_PER_WARP (N_RULES / NWARPS)   // 256
#define NBLOCKS (BATCH / BT)                // 128

// Dynamic smem layout (floats):
//  Cs    [4096*8]  coeff padded 7->8, LDS.128-able      (131072 B)
//  Psh   [64*32]   high-digit triple products, [h][lane]
//  Qsh   [64*32]   low-digit triple products,  [lo][lane]
//  xpsh  [7*32]    x_plus, [j][lane]
//  rdsh  [32]      1/denominator
//  accsh [16*7*32] per-warp partial accumulators
#define CS_F    (N_RULES * 8)
#define P_F     (64 * BT)
#define Q_F     (64 * BT)
#define XP_F    (7 * BT)
#define RD_F    (BT)
#define ACC_F   (NWARPS * 7 * BT)
#define SMEM_FLOATS (CS_F + P_F + Q_F + XP_F + RD_F + ACC_F)
#define SMEM_BYTES  (SMEM_FLOATS * 4)

__device__ __forceinline__ uint32_t s2u(const void* p) {
    return (uint32_t)__cvta_generic_to_shared(p);
}

__global__ void __launch_bounds__(NTHREADS, 1) anfis_fused_kernel(
    const float* __restrict__ x, const float* __restrict__ a,
    const float* __restrict__ b, const float* __restrict__ c,
    const float* __restrict__ coeff, float* __restrict__ out)
{
    extern __shared__ float smem[];
    float* Cs    = smem;
    float* Psh   = Cs + CS_F;
    float* Qsh   = Psh + P_F;
    float* xpsh  = Qsh + Q_F;
    float* rdsh  = xpsh + XP_F;
    float* accsh = rdsh + RD_F;

    const int tid  = threadIdx.x;
    const int lane = tid & 31;
    const int wid  = tid >> 5;
    const int b0   = blockIdx.x * BT;

    // ---- Stage coeff into smem, padded to 8 floats/rule (all 512 threads) ----
    #pragma unroll
    for (int it = 0; it < (N_RULES * 7 + NTHREADS - 1) / NTHREADS; it++) {
        int idx = it * NTHREADS + tid;
        if (idx < N_RULES * 7) {
            int r = idx / 7;
            int j = idx - r * 7;
            Cs[r * 8 + j] = coeff[idx];
        }
    }
    #pragma unroll
    for (int it = 0; it < N_RULES / NTHREADS; it++)
        Cs[(it * NTHREADS + tid) * 8 + 7] = 0.0f;

    // ---- Phase 1 (parallel over all 16 warps): memberships, P/Q, den ----
    {
        const int bb = b0 + lane;
        float m[N_IN][N_MF];
        float den = 1.0f;
        #pragma unroll
        for (int i = 0; i < N_IN; i++) {
            float xi = __ldg(&x[bb * N_IN + i]);
            if (wid == 0) xpsh[i * BT + lane] = xi;
            float s = 0.0f;
            #pragma unroll
            for (int k = 0; k < N_MF; k++) {
                float av = __ldg(&a[i * N_MF + k]);
                float bv = __ldg(&b[i * N_MF + k]);
                float cv = __ldg(&c[i * N_MF + k]);
                float d  = (xi - cv) / av;
                float d2 = d * d;
                float db = (bv == 2.0f) ? (d2 * d2) : __powf(d2, bv);
                float mm = 1.0f / (1.0f + db);
                m[i][k] = mm;
                s += mm;
            }
            den *= s;
        }
        if (wid == 0) {
            xpsh[6 * BT + lane] = 1.0f;
            rdsh[lane] = 1.0f / fmaxf(den, 1e-12f);
        }
        // each warp fills 4 of the 64 rows of Psh and Qsh
        #pragma unroll
        for (int hh = 0; hh < 4; hh++) {
            int h = wid * 4 + hh;
            Psh[h * BT + lane] = m[0][(h >> 4) & 3] * m[1][(h >> 2) & 3] * m[2][h & 3];
            Qsh[h * BT + lane] = m[3][(h >> 4) & 3] * m[4][(h >> 2) & 3] * m[5][h & 3];
        }
    }
    __syncthreads();

    // ---- Phase 2: rule loop. acc_j = sum_r w(b,r)*coeff[r,j], f32x2 packed ----
    unsigned long long acc01 = 0ull, acc23 = 0ull, acc45 = 0ull, acc67 = 0ull;

    #pragma unroll
    for (int hh = 0; hh < RULES_PER_WARP / 64; hh++) {   // 4 high-digit groups
        const int rhi = wid * (RULES_PER_WARP / 64) + hh;
        const float Pv = Psh[rhi * BT + lane];
        const uint32_t cb = s2u(Cs + rhi * 64 * 8);      // 64 rules * 32 bytes... *4
        #pragma unroll 8
        for (int lo = 0; lo < 64; lo++) {
            float q = Qsh[lo * BT + lane];
            float w = Pv * q;
            unsigned long long ww, c0, c1, c2, c3;
            asm("mov.b64 %0, {%1, %1};" : "=l"(ww) : "f"(w));
            uint32_t ca = cb + lo * 32;
            asm("ld.shared.v2.u64 {%0, %1}, [%2];"      : "=l"(c0), "=l"(c1) : "r"(ca));
            asm("ld.shared.v2.u64 {%0, %1}, [%2+16];"   : "=l"(c2), "=l"(c3) : "r"(ca));
            asm("fma.rn.f32x2 %0, %1, %2, %0;" : "+l"(acc01) : "l"(ww), "l"(c0));
            asm("fma.rn.f32x2 %0, %1, %2, %0;" : "+l"(acc23) : "l"(ww), "l"(c1));
            asm("fma.rn.f32x2 %0, %1, %2, %0;" : "+l"(acc45) : "l"(ww), "l"(c2));
            asm("fma.rn.f32x2 %0, %1, %2, %0;" : "+l"(acc67) : "l"(ww), "l"(c3));
        }
    }

    // unpack and stash per-warp partials
    {
        float a0, a1, a2, a3, a4, a5, a6, a7;
        asm("mov.b64 {%0, %1}, %2;" : "=f"(a0), "=f"(a1) : "l"(acc01));
        asm("mov.b64 {%0, %1}, %2;" : "=f"(a2), "=f"(a3) : "l"(acc23));
        asm("mov.b64 {%0, %1}, %2;" : "=f"(a4), "=f"(a5) : "l"(acc45));
        asm("mov.b64 {%0, %1}, %2;" : "=f"(a6), "=f"(a7) : "l"(acc67));
        float* A = accsh + (wid * 7) * BT + lane;
        A[0 * BT] = a0; A[1 * BT] = a1; A[2 * BT] = a2; A[3 * BT] = a3;
        A[4 * BT] = a4; A[5 * BT] = a5; A[6 * BT] = a6;
        (void)a7; // padding lane
    }
    __syncthreads();

    // ---- Phase 3: cross-warp reduce, dot with x_plus, scale, write out ----
    if (tid < BT) {
        float num = 0.0f;
        #pragma unroll
        for (int j = 0; j < 7; j++) {
            float D = 0.0f;
            #pragma unroll
            for (int w = 0; w < NWARPS; w++)
                D += accsh[(w * 7 + j) * BT + tid];
            num = fmaf(xpsh[j * BT + tid], D, num);
        }
        out[b0 + tid] = num * rdsh[tid];
    }
}

extern "C" void kernel_launch(void* const* d_in, const int* in_sizes, int n_in,
                              void* d_out, int out_size) {
    const float* x     = (const float*)d_in[0];
    const float* a     = (const float*)d_in[1];
    const float* b     = (const float*)d_in[2];
    const float* c     = (const float*)d_in[3];
    const float* coeff = (const float*)d_in[4];
    // d_in[5] = mf_indices: full itertools.product enumeration -> base-4 digit
    // decode is analytic, index tensor unused.
    float* out = (float*)d_out;

    static bool attr_set = false;
    if (!attr_set) {
        cudaFuncSetAttribute(anfis_fused_kernel,
                             cudaFuncAttributeMaxDynamicSharedMemorySize, SMEM_BYTES);
        attr_set = true;
    }
    anfis_fused_kernel<<<NBLOCKS, NTHREADS, SMEM_BYTES>>>(x, a, b, c, coeff, out);
}

// round 3
// speedup vs baseline: 1.4842x; 1.0513x over previous
#include <cuda_runtime.h>
#include <cstdint>

#define N_IN    6
#define N_MF    4
#define N_RULES 4096
#define BATCH   4096
#define BT      32
#define NWARPS  16
#define NTHREADS (NWARPS * 32)
#define NPAIRS_PER_WARP 128                 // 256 rules / 2
#define NBLOCKS (BATCH / BT)                // 128

// smem: Cs[4096 rules -> 2048 pairs * 16 floats] + msh[3*4*32] + accsh[16*7*32]
#define CS_F   (2048 * 16)
#define MSH_F  (3 * 4 * BT)
#define ACC_F  (NWARPS * 7 * BT)
#define SMEM_BYTES ((CS_F + MSH_F + ACC_F) * 4)

__device__ __forceinline__ uint32_t s2u(const void* p) {
    return (uint32_t)__cvta_generic_to_shared(p);
}
__device__ __forceinline__ unsigned long long pk2(float lo, float hi) {
    unsigned long long r;
    asm("mov.b64 %0, {%1, %2};" : "=l"(r) : "f"(lo), "f"(hi));
    return r;
}

__global__ void __launch_bounds__(NTHREADS, 1) anfis_fused_kernel(
    const float* __restrict__ x, const float* __restrict__ a,
    const float* __restrict__ b, const float* __restrict__ c,
    const float* __restrict__ coeff, float* __restrict__ out)
{
    extern __shared__ float smem[];
    float* Cs    = smem;                 // pair p: [j0r0,j0r1,j1r0,j1r1,...,j6r0,j6r1,pad,pad]
    float* msh   = Cs + CS_F;            // memberships for inputs 0..2: [i][k][lane]
    float* accsh = msh + MSH_F;          // [warp][j][lane]

    const int tid  = threadIdx.x;
    const int lane = tid & 31;
    const int wid  = tid >> 5;
    const int b0   = blockIdx.x * BT;

    // ---- Stage coeff, j-interleaved by rule pair (paired 8B shared stores) ----
    // t enumerates (pair p, j): reads coeff[2p*7+j], coeff[(2p+1)*7+j]
    for (int t = tid; t < 2048 * 7; t += NTHREADS) {
        int p = t / 7;
        int j = t - p * 7;
        float e = __ldg(&coeff[p * 14 + j]);
        float o = __ldg(&coeff[p * 14 + 7 + j]);
        unsigned long long v = pk2(e, o);
        asm volatile("st.shared.u64 [%0], %1;"
                     :: "r"(s2u(Cs + p * 16 + j * 2)), "l"(v));
    }

    // ---- Phase 1: memberships (all warps, same 32 batch lanes), all in regs ----
    const int bb = b0 + lane;
    float xi[N_IN];
    float mm[N_IN][N_MF];
    float den = 1.0f;
    #pragma unroll
    for (int i = 0; i < N_IN; i++) {
        xi[i] = __ldg(&x[bb * N_IN + i]);
        float s = 0.0f;
        #pragma unroll
        for (int k = 0; k < N_MF; k++) {
            float av = __ldg(&a[i * N_MF + k]);
            float bv = __ldg(&b[i * N_MF + k]);
            float cv = __ldg(&c[i * N_MF + k]);
            float d  = (xi[i] - cv) / av;
            float d2 = d * d;
            float db = (bv == 2.0f) ? (d2 * d2) : __powf(d2, bv);
            float mv = 1.0f / (1.0f + db);
            mm[i][k] = mv;
            s += mv;
        }
        den *= s;
    }
    const float rden = 1.0f / fmaxf(den, 1e-12f);

    // share memberships of inputs 0..2 (needed with runtime digit index for Pv)
    if (wid == 0) {
        #pragma unroll
        for (int i = 0; i < 3; i++)
            #pragma unroll
            for (int k = 0; k < N_MF; k++)
                msh[(i * N_MF + k) * BT + lane] = mm[i][k];
    }

    // ---- Build packed Q pairs: Qp[m] = (Q[2m], Q[2m+1]), all constant-indexed ----
    unsigned long long m5p0 = pk2(mm[5][0], mm[5][1]);
    unsigned long long m5p1 = pk2(mm[5][2], mm[5][3]);
    unsigned long long Qp[32];
    #pragma unroll
    for (int ab = 0; ab < 16; ab++) {
        float tt = mm[3][ab >> 2] * mm[4][ab & 3];
        unsigned long long ttp = pk2(tt, tt);
        asm("mul.rn.f32x2 %0, %1, %2;" : "=l"(Qp[2 * ab])     : "l"(ttp), "l"(m5p0));
        asm("mul.rn.f32x2 %0, %1, %2;" : "=l"(Qp[2 * ab + 1]) : "l"(ttp), "l"(m5p1));
    }
    __syncthreads();

    // ---- Phase 2: 4 high-digit groups x 32 pairs; 12 issues per pair ----
    unsigned long long acc[7];
    #pragma unroll
    for (int j = 0; j < 7; j++) acc[j] = 0ull;

    const uint32_t cwbase = s2u(Cs) + (uint32_t)wid * (NPAIRS_PER_WARP * 64);

    #pragma unroll 1
    for (int hh = 0; hh < 4; hh++) {
        const int rhi = wid * 4 + hh;
        const float Pv = msh[(0 * N_MF + ((rhi >> 4) & 3)) * BT + lane]
                       * msh[(1 * N_MF + ((rhi >> 2) & 3)) * BT + lane]
                       * msh[(2 * N_MF + (rhi & 3)) * BT + lane];
        const unsigned long long PP = pk2(Pv, Pv);
        const uint32_t cb = cwbase + (uint32_t)hh * (32 * 64);
        #pragma unroll
        for (int m = 0; m < 32; m++) {
            unsigned long long ww, c0, c1, c2, c3, c4, c5, c6;
            asm("mul.rn.f32x2 %0, %1, %2;" : "=l"(ww) : "l"(PP), "l"(Qp[m]));
            const uint32_t ca = cb + m * 64;
            asm("ld.shared.v2.u64 {%0, %1}, [%2];"    : "=l"(c0), "=l"(c1) : "r"(ca));
            asm("ld.shared.v2.u64 {%0, %1}, [%2+16];" : "=l"(c2), "=l"(c3) : "r"(ca));
            asm("ld.shared.v2.u64 {%0, %1}, [%2+32];" : "=l"(c4), "=l"(c5) : "r"(ca));
            asm("ld.shared.u64 %0, [%1+48];"          : "=l"(c6)           : "r"(ca));
            asm("fma.rn.f32x2 %0, %1, %2, %0;" : "+l"(acc[0]) : "l"(ww), "l"(c0));
            asm("fma.rn.f32x2 %0, %1, %2, %0;" : "+l"(acc[1]) : "l"(ww), "l"(c1));
            asm("fma.rn.f32x2 %0, %1, %2, %0;" : "+l"(acc[2]) : "l"(ww), "l"(c2));
            asm("fma.rn.f32x2 %0, %1, %2, %0;" : "+l"(acc[3]) : "l"(ww), "l"(c3));
            asm("fma.rn.f32x2 %0, %1, %2, %0;" : "+l"(acc[4]) : "l"(ww), "l"(c4));
            asm("fma.rn.f32x2 %0, %1, %2, %0;" : "+l"(acc[5]) : "l"(ww), "l"(c5));
            asm("fma.rn.f32x2 %0, %1, %2, %0;" : "+l"(acc[6]) : "l"(ww), "l"(c6));
        }
    }

    // ---- fold even/odd-rule halves, stash per-warp partials ----
    #pragma unroll
    for (int j = 0; j < 7; j++) {
        float e, o;
        asm("mov.b64 {%0, %1}, %2;" : "=f"(e), "=f"(o) : "l"(acc[j]));
        accsh[(wid * 7 + j) * BT + lane] = e + o;
    }
    __syncthreads();

    // ---- Phase 3: cross-warp reduce + TSK dot + normalize (warp 0 only) ----
    if (wid == 0) {
        float num = 0.0f;
        #pragma unroll
        for (int j = 0; j < 7; j++) {
            float D = 0.0f;
            #pragma unroll
            for (int w = 0; w < NWARPS; w++)
                D += accsh[(w * 7 + j) * BT + lane];
            float xp = (j < 6) ? xi[j] : 1.0f;
            num = fmaf(xp, D, num);
        }
        out[b0 + lane] = num * rden;
    }
}

extern "C" void kernel_launch(void* const* d_in, const int* in_sizes, int n_in,
                              void* d_out, int out_size) {
    const float* x     = (const float*)d_in[0];
    const float* a     = (const float*)d_in[1];
    const float* b     = (const float*)d_in[2];
    const float* c     = (const float*)d_in[3];
    const float* coeff = (const float*)d_in[4];
    // d_in[5] = mf_indices: full itertools.product enumeration; digit decode is analytic.
    float* out = (float*)d_out;

    static bool attr_set = false;
    if (!attr_set) {
        cudaFuncSetAttribute(anfis_fused_kernel,
                             cudaFuncAttributeMaxDynamicSharedMemorySize, SMEM_BYTES);
        attr_set = true;
    }
    anfis_fused_kernel<<<NBLOCKS, NTHREADS, SMEM_BYTES>>>(x, a, b, c, coeff, out);
}